// round 6
// baseline (speedup 1.0000x reference)
#include <cuda_runtime.h>
#include <math.h>

#define H 128
#define MAXB 8192
#define RPB 16   // rows per block in the MLP kernel

__device__ float g_sent[(size_t)MAXB * H];

// ---------------------------------------------------------------------------
// Kernel 1: gather + segment mean. One CTA per segment. Segment bounds via
// inline binary search over the sorted segment_ids (top of the search tree is
// L2-hot across all 4096 blocks; the dependent-load chains overlap across the
// ~16 resident blocks per SM).
// Gather: warp w takes tokens i = w, w+4, ...; lane l holds dims 4l..4l+3 as
// float4 -> pure LDG.128 traffic, 4 loads in flight per warp.
// ---------------------------------------------------------------------------
__global__ __launch_bounds__(128) void seg_mean_kernel(
    const int*   __restrict__ token_ids,
    const int*   __restrict__ seg_ids,
    const float* __restrict__ embed,
    int T)
{
    const int seg = blockIdx.x;
    const int tid = threadIdx.x;
    const int w   = tid >> 5;
    const int l   = tid & 31;

    // lower_bound(seg), lower_bound(seg+1) — all threads redundantly (broadcast)
    int lo = 0, hi = T;
    while (lo < hi) {
        int mid = (lo + hi) >> 1;
        if (__ldg(&seg_ids[mid]) < seg) lo = mid + 1; else hi = mid;
    }
    const int start = lo;
    hi = T;
    while (lo < hi) {
        int mid = (lo + hi) >> 1;
        if (__ldg(&seg_ids[mid]) < seg + 1) lo = mid + 1; else hi = mid;
    }
    const int end = lo;

    __shared__ int   s_tok[128];
    __shared__ float s_part[4 * H];

    const float4* E4 = (const float4*)embed;   // row = 32 float4

    float4 a0 = make_float4(0.f, 0.f, 0.f, 0.f), a1 = a0, a2 = a0, a3 = a0;

    for (int t0 = start; t0 < end; t0 += 128) {
        const int n = min(128, end - t0);
        __syncthreads();
        if (tid < n) s_tok[tid] = token_ids[t0 + tid];
        __syncthreads();
        int i = w;
        for (; i + 12 < n; i += 16) {        // 4 loads in flight per warp
            const float4 r0 = __ldg(&E4[(size_t)s_tok[i +  0] * 32 + l]);
            const float4 r1 = __ldg(&E4[(size_t)s_tok[i +  4] * 32 + l]);
            const float4 r2 = __ldg(&E4[(size_t)s_tok[i +  8] * 32 + l]);
            const float4 r3 = __ldg(&E4[(size_t)s_tok[i + 12] * 32 + l]);
            a0.x += r0.x; a0.y += r0.y; a0.z += r0.z; a0.w += r0.w;
            a1.x += r1.x; a1.y += r1.y; a1.z += r1.z; a1.w += r1.w;
            a2.x += r2.x; a2.y += r2.y; a2.z += r2.z; a2.w += r2.w;
            a3.x += r3.x; a3.y += r3.y; a3.z += r3.z; a3.w += r3.w;
        }
        for (; i < n; i += 4) {
            const float4 r = __ldg(&E4[(size_t)s_tok[i] * 32 + l]);
            a0.x += r.x; a0.y += r.y; a0.z += r.z; a0.w += r.w;
        }
    }

    float4 asum;
    asum.x = (a0.x + a1.x) + (a2.x + a3.x);
    asum.y = (a0.y + a1.y) + (a2.y + a3.y);
    asum.z = (a0.z + a1.z) + (a2.z + a3.z);
    asum.w = (a0.w + a1.w) + (a2.w + a3.w);
    *(float4*)&s_part[w * H + 4 * l] = asum;
    __syncthreads();

    const float inv = 1.0f / (float)max(end - start, 1);
    g_sent[(size_t)seg * H + tid] =
        ((s_part[tid] + s_part[H + tid]) +
         (s_part[2 * H + tid] + s_part[3 * H + tid])) * inv;
}

// ---------------------------------------------------------------------------
// Kernel 2: batched GEMV + tanh + dot(W_out) + BCE. 16 rows per 256-thread
// block. Thread t owns output column (t&127) for the 8 rows of its half.
// Sentence tile transposed in smem: k-loop = 1 LDG + 2 broadcast LDS.128
// + 8 FMA. W traffic = 256 blocks x 64KB = 16MB (L1/L2-hot).
// ---------------------------------------------------------------------------
__global__ __launch_bounds__(256) void mlp_bce_kernel(
    const float* __restrict__ y_true,
    const float* __restrict__ W_hid,   // [H,H] row-major
    const float* __restrict__ b_hid,
    const float* __restrict__ W_out,
    const float* __restrict__ b_out,
    float*       __restrict__ out,
    int B)
{
    const int t    = threadIdx.x;
    const int row0 = blockIdx.x * RPB;

    __shared__ float s_t[H][RPB];      // transposed sentence tile (8 KB)
    __shared__ float red[2][8][4];     // [grp][local row][warp-in-grp]

    for (int e = t; e < RPB * H; e += 256) {
        const int r = e >> 7;          // 0..15
        const int k = e & 127;
        const int row = min(row0 + r, B - 1);
        s_t[k][r] = g_sent[(size_t)row * H + k];
    }
    __syncthreads();

    const int col = t & 127;
    const int grp = t >> 7;            // 0/1: local rows grp*8 .. grp*8+7

    float acc[8];
    const float bh = b_hid[col];
#pragma unroll
    for (int r = 0; r < 8; r++) acc[r] = bh;

#pragma unroll 4
    for (int k = 0; k < H; k++) {
        const float  wv = __ldg(&W_hid[k * H + col]);
        const float4 sa = *(const float4*)&s_t[k][grp * 8 + 0];   // broadcast
        const float4 sb = *(const float4*)&s_t[k][grp * 8 + 4];
        acc[0] += sa.x * wv;  acc[1] += sa.y * wv;
        acc[2] += sa.z * wv;  acc[3] += sa.w * wv;
        acc[4] += sb.x * wv;  acc[5] += sb.y * wv;
        acc[6] += sb.z * wv;  acc[7] += sb.w * wv;
    }

    const float wo = W_out[col];
    float val[8];
#pragma unroll
    for (int r = 0; r < 8; r++)
        val[r] = tanhf(acc[r]) * wo;

#pragma unroll
    for (int off = 16; off > 0; off >>= 1)
#pragma unroll
        for (int r = 0; r < 8; r++)
            val[r] += __shfl_xor_sync(0xffffffffu, val[r], off);

    const int lane = t & 31;
    const int wig  = (t >> 5) & 3;
    if (lane == 0)
#pragma unroll
        for (int r = 0; r < 8; r++) red[grp][r][wig] = val[r];
    __syncthreads();

    if (t < RPB) {
        const int g  = t >> 3;
        const int rr = t & 7;
        const int row = row0 + t;
        float loss = 0.f;
        if (row < B) {
            const float z = (red[g][rr][0] + red[g][rr][1]) +
                            (red[g][rr][2] + red[g][rr][3]) + __ldg(b_out);
            const float lp  = fmaxf(-log1pf(expf(-z)), -100.0f);
            const float l1m = fmaxf(-log1pf(expf(z)),  -100.0f);
            const float y   = y_true[row];
            loss = -(y * lp + (1.0f - y) * l1m);
        }
#pragma unroll
        for (int off = 8; off > 0; off >>= 1)
            loss += __shfl_xor_sync(0x0000ffffu, loss, off);
        if (t == 0) atomicAdd(out, loss);
    }
}

// ---------------------------------------------------------------------------
extern "C" void kernel_launch(void* const* d_in, const int* in_sizes, int n_in,
                              void* d_out, int out_size)
{
    const int*   token_ids = (const int*)d_in[0];
    const int*   seg_ids   = (const int*)d_in[1];
    const float* y_true    = (const float*)d_in[2];
    const float* embed     = (const float*)d_in[3];
    const float* W_hid     = (const float*)d_in[4];
    const float* b_hid     = (const float*)d_in[5];
    const float* W_out     = (const float*)d_in[6];
    const float* b_out     = (const float*)d_in[7];

    const int T = in_sizes[0];
    const int B = in_sizes[2];
    float* out = (float*)d_out;

    cudaMemsetAsync(out, 0, sizeof(float));

    seg_mean_kernel<<<B, 128>>>(token_ids, seg_ids, embed, T);

    mlp_bce_kernel<<<(B + RPB - 1) / RPB, 256>>>(y_true, W_hid, b_hid,
                                                 W_out, b_out, out, B);
}

// round 7
// speedup vs baseline: 1.2556x; 1.2556x over previous
#include <cuda_runtime.h>
#include <math.h>

#define H 128
#define MAXB 8192
#define RPB 8                     // segments per MLP group
#define NGRP (MAXB / RPB)

__device__ int   g_starts[MAXB + 1];
__device__ float g_sent[(size_t)MAXB * H];
__device__ int   g_cnt[NGRP];

// ---------------------------------------------------------------------------
// Kernel 0: vectorized prepass. Builds g_starts from sorted segment_ids
// (int4 loads, 4 tokens/thread), zeroes the group counters and the output.
// ---------------------------------------------------------------------------
__global__ __launch_bounds__(256) void prepass_kernel(
    const int* __restrict__ seg_ids, float* __restrict__ out, int T, int B)
{
    const int gid = blockIdx.x * blockDim.x + threadIdx.x;

    // zero group counters + output (block 0)
    if (blockIdx.x == 0) {
        const int ngrp = (B + RPB - 1) / RPB;
        for (int g = threadIdx.x; g < ngrp; g += 256) g_cnt[g] = 0;
        if (threadIdx.x == 0) *out = 0.0f;
    }

    const int i0 = gid * 4;
    if (i0 >= T) return;

    int v[4];
    if (i0 + 3 < T) {
        const int4 q = __ldg(&((const int4*)seg_ids)[gid]);
        v[0] = q.x; v[1] = q.y; v[2] = q.z; v[3] = q.w;
    } else {
        for (int j = 0; j < 4; j++)
            v[j] = (i0 + j < T) ? __ldg(&seg_ids[i0 + j]) : v[j > 0 ? j - 1 : 0];
    }

    int prev = (i0 == 0) ? -1 : __ldg(&seg_ids[i0 - 1]);
#pragma unroll
    for (int j = 0; j < 4; j++) {
        const int i = i0 + j;
        if (i >= T) break;
        const int cur = v[j];
        for (int s = prev + 1; s <= cur; s++) g_starts[s] = i;
        if (i == T - 1)
            for (int s = cur + 1; s <= B; s++) g_starts[s] = T;
        prev = cur;
    }
}

// ---------------------------------------------------------------------------
// Kernel 1 (fused): gather + segment-mean; the LAST-arriving block of every
// 8-segment group also runs the MLP head + BCE for those 8 rows
// (threadfence-reduction pattern). The MLP work hides under concurrent
// gathers; only the final group's tail is exposed.
// ---------------------------------------------------------------------------
__global__ __launch_bounds__(128, 12) void fused_dan_kernel(
    const int*   __restrict__ token_ids,
    const float* __restrict__ embed,
    const float* __restrict__ y_true,
    const float* __restrict__ W_hid,   // [H,H] row-major
    const float* __restrict__ b_hid,
    const float* __restrict__ W_out,
    const float* __restrict__ b_out,
    float*       __restrict__ out,
    int B)
{
    const int seg = blockIdx.x;
    const int tid = threadIdx.x;
    const int w   = tid >> 5;
    const int l   = tid & 31;

    const int start = __ldg(&g_starts[seg]);
    const int end   = __ldg(&g_starts[seg + 1]);

    __shared__ int   s_tok[128];
    __shared__ float s_part[4 * H];
    __shared__ float s_t[H][RPB];     // transposed group tile for the MLP tail
    __shared__ float s_red[4];
    __shared__ int   s_last;

    const float4* E4 = (const float4*)embed;    // row = 32 float4

    // ---- gather: warp-strided tokens, LDG.128, 4 loads in flight ----
    float4 a0 = make_float4(0.f, 0.f, 0.f, 0.f), a1 = a0, a2 = a0, a3 = a0;

    for (int t0 = start; t0 < end; t0 += 128) {
        const int n = min(128, end - t0);
        __syncthreads();
        if (tid < n) s_tok[tid] = token_ids[t0 + tid];
        __syncthreads();
        int i = w;
        for (; i + 12 < n; i += 16) {
            const float4 r0 = __ldg(&E4[(size_t)s_tok[i +  0] * 32 + l]);
            const float4 r1 = __ldg(&E4[(size_t)s_tok[i +  4] * 32 + l]);
            const float4 r2 = __ldg(&E4[(size_t)s_tok[i +  8] * 32 + l]);
            const float4 r3 = __ldg(&E4[(size_t)s_tok[i + 12] * 32 + l]);
            a0.x += r0.x; a0.y += r0.y; a0.z += r0.z; a0.w += r0.w;
            a1.x += r1.x; a1.y += r1.y; a1.z += r1.z; a1.w += r1.w;
            a2.x += r2.x; a2.y += r2.y; a2.z += r2.z; a2.w += r2.w;
            a3.x += r3.x; a3.y += r3.y; a3.z += r3.z; a3.w += r3.w;
        }
        for (; i < n; i += 4) {
            const float4 r = __ldg(&E4[(size_t)s_tok[i] * 32 + l]);
            a0.x += r.x; a0.y += r.y; a0.z += r.z; a0.w += r.w;
        }
    }

    float4 asum;
    asum.x = (a0.x + a1.x) + (a2.x + a3.x);
    asum.y = (a0.y + a1.y) + (a2.y + a3.y);
    asum.z = (a0.z + a1.z) + (a2.z + a3.z);
    asum.w = (a0.w + a1.w) + (a2.w + a3.w);
    *(float4*)&s_part[w * H + 4 * l] = asum;
    __syncthreads();

    const float inv = 1.0f / (float)max(end - start, 1);
    g_sent[(size_t)seg * H + tid] =
        ((s_part[tid] + s_part[H + tid]) +
         (s_part[2 * H + tid] + s_part[3 * H + tid])) * inv;

    // ---- group rendezvous (threadfence-reduction pattern) ----
    const int grp = seg / RPB;
    __threadfence();
    if (tid == 0)
        s_last = (atomicAdd(&g_cnt[grp], 1) == RPB - 1);
    __syncthreads();
    if (!s_last) return;
    __threadfence();   // acquire side: make peers' g_sent writes visible

    // ---- MLP + BCE for rows grp*RPB .. grp*RPB+7 ----
    const int row0 = grp * RPB;
#pragma unroll
    for (int r = 0; r < RPB; r++) {
        const int row = min(row0 + r, B - 1);
        s_t[tid][r] = g_sent[(size_t)row * H + tid];
    }
    __syncthreads();

    float acc[RPB];
    const float bh = b_hid[tid];
#pragma unroll
    for (int r = 0; r < RPB; r++) acc[r] = bh;

#pragma unroll 4
    for (int k = 0; k < H; k++) {
        const float  wv = __ldg(&W_hid[k * H + tid]);
        const float4 sa = *(const float4*)&s_t[k][0];   // broadcast LDS.128
        const float4 sb = *(const float4*)&s_t[k][4];
        acc[0] += sa.x * wv;  acc[1] += sa.y * wv;
        acc[2] += sa.z * wv;  acc[3] += sa.w * wv;
        acc[4] += sb.x * wv;  acc[5] += sb.y * wv;
        acc[6] += sb.z * wv;  acc[7] += sb.w * wv;
    }

    const float wo = W_out[tid];
    float val[RPB];
#pragma unroll
    for (int r = 0; r < RPB; r++)
        val[r] = tanhf(acc[r]) * wo;

#pragma unroll
    for (int off = 16; off > 0; off >>= 1)
#pragma unroll
        for (int r = 0; r < RPB; r++)
            val[r] += __shfl_xor_sync(0xffffffffu, val[r], off);

    // stash per-warp partials: warp w writes val[r] for all r at s_t[r][w]
    if (l == 0)
#pragma unroll
        for (int r = 0; r < RPB; r++) s_t[r][w] = val[r];   // reuse s_t as scratch
    __syncthreads();

    if (tid < RPB) {
        const int row = row0 + tid;
        float loss = 0.f;
        if (row < B) {
            const float z = (s_t[tid][0] + s_t[tid][1]) +
                            (s_t[tid][2] + s_t[tid][3]) + __ldg(b_out);
            const float lp  = fmaxf(-log1pf(expf(-z)), -100.0f);
            const float l1m = fmaxf(-log1pf(expf(z)),  -100.0f);
            const float y   = __ldg(&y_true[row]);
            loss = -(y * lp + (1.0f - y) * l1m);
        }
#pragma unroll
        for (int off = 4; off > 0; off >>= 1)
            loss += __shfl_xor_sync(0x000000ffu, loss, off);
        if (tid == 0) atomicAdd(out, loss);
    }
}

// ---------------------------------------------------------------------------
extern "C" void kernel_launch(void* const* d_in, const int* in_sizes, int n_in,
                              void* d_out, int out_size)
{
    const int*   token_ids = (const int*)d_in[0];
    const int*   seg_ids   = (const int*)d_in[1];
    const float* y_true    = (const float*)d_in[2];
    const float* embed     = (const float*)d_in[3];
    const float* W_hid     = (const float*)d_in[4];
    const float* b_hid     = (const float*)d_in[5];
    const float* W_out     = (const float*)d_in[6];
    const float* b_out     = (const float*)d_in[7];

    const int T = in_sizes[0];
    const int B = in_sizes[2];
    float* out = (float*)d_out;

    const int vthreads = (T + 3) / 4;
    prepass_kernel<<<(vthreads + 255) / 256, 256>>>(seg_ids, out, T, B);

    fused_dan_kernel<<<B, 128>>>(token_ids, embed, y_true,
                                 W_hid, b_hid, W_out, b_out, out, B);
}

// round 9
// speedup vs baseline: 1.5733x; 1.2530x over previous
#include <cuda_runtime.h>
#include <cstdint>
#include <math.h>

#define H 128
#define MAXB 8192
#define RPB 8   // rows per MLP block

__device__ int   g_starts[MAXB + 1];
__device__ float g_sent[(size_t)MAXB * H];

#define CP_ASYNC_CG(dst_u32, src_ptr) \
    asm volatile("cp.async.cg.shared.global [%0], [%1], 16;" :: "r"(dst_u32), "l"(src_ptr))
#define CP_COMMIT() asm volatile("cp.async.commit_group;")
#define CP_WAIT1()  asm volatile("cp.async.wait_group 1;" ::: "memory")

// ---------------------------------------------------------------------------
// Kernel 0: vectorized prepass. Builds g_starts from sorted segment_ids
// (int4 loads) and zeroes the output scalar (no separate memset launch).
// ---------------------------------------------------------------------------
__global__ __launch_bounds__(256) void prepass_kernel(
    const int* __restrict__ seg_ids, float* __restrict__ out, int T, int B)
{
    const int gid = blockIdx.x * blockDim.x + threadIdx.x;
    if (gid == 0) *out = 0.0f;

    const int i0 = gid * 4;
    if (i0 >= T) return;

    int v[4];
    if (i0 + 3 < T) {
        const int4 q = __ldg(&((const int4*)seg_ids)[gid]);
        v[0] = q.x; v[1] = q.y; v[2] = q.z; v[3] = q.w;
    } else {
        for (int j = 0; j < 4; j++)
            v[j] = (i0 + j < T) ? __ldg(&seg_ids[i0 + j]) : v[j > 0 ? j - 1 : 0];
    }

    int prev = (i0 == 0) ? -1 : __ldg(&seg_ids[i0 - 1]);
#pragma unroll
    for (int j = 0; j < 4; j++) {
        const int i = i0 + j;
        if (i >= T) break;
        const int cur = v[j];
        for (int s = prev + 1; s <= cur; s++) g_starts[s] = i;
        if (i == T - 1)
            for (int s = cur + 1; s <= B; s++) g_starts[s] = T;
        prev = cur;
    }
}

// ---------------------------------------------------------------------------
// Kernel 1: gather + segment mean via cp.async double-buffering.
// One CTA per segment. Warp w owns rows c*16 + 4w + {0..3} of its segment.
// In-flight bytes live in SMEM (not registers) -> low regs + high occupancy
// + 8 rows (4KB) in flight per warp. Warp-private pipeline: NO barriers in
// the mainloop. Consume = LDS.128 (lane l reads exactly the bytes it copied).
// ---------------------------------------------------------------------------
__global__ __launch_bounds__(128) void seg_mean_kernel(
    const int*   __restrict__ token_ids,
    const float* __restrict__ embed)
{
    const int seg = blockIdx.x;
    const int tid = threadIdx.x;
    const int w   = tid >> 5;
    const int l   = tid & 31;

    const int start = __ldg(&g_starts[seg]);
    const int end   = __ldg(&g_starts[seg + 1]);
    const int n     = end - start;
    const int chunks = (n + 15) >> 4;

    __shared__ __align__(16) float4 s_buf[4][2][4][32];  // [warp][slot][row][lane] 16KB
    __shared__ float s_part[4][H];

    const unsigned int sbase =
        (unsigned int)__cvta_generic_to_shared(&s_buf[w][0][0][l]);
    const char* E = (const char*)embed;

    float4 a0 = make_float4(0.f, 0.f, 0.f, 0.f), a1 = a0;

    // producer for chunk c into slot c&1 (commits even when empty)
#define FILL(c)                                                            \
    do {                                                                   \
        const int _c = (c);                                                \
        if (_c < chunks) {                                                 \
            const int _base = start + _c * 16 + w * 4;                     \
            _Pragma("unroll")                                              \
            for (int _j = 0; _j < 4; _j++) {                               \
                const int _idx = _base + _j;                               \
                if (_idx < end) {                                          \
                    const int _tok = __ldg(&token_ids[_idx]);              \
                    CP_ASYNC_CG(sbase + (unsigned int)((_c & 1) * 2048 + _j * 512), \
                                E + (size_t)_tok * 512 + l * 16);          \
                }                                                          \
            }                                                              \
        }                                                                  \
        CP_COMMIT();                                                       \
    } while (0)

    FILL(0);
    FILL(1);

    for (int c = 0; c < chunks; c++) {
        CP_WAIT1();                          // chunk c complete (c+1 may pend)
        const int base = c * 16 + w * 4;     // local row index
        const int m    = n - base;           // valid rows for this warp (<=4)
        const int slot = c & 1;
        if (m >= 1) { const float4 v = s_buf[w][slot][0][l];
                      a0.x += v.x; a0.y += v.y; a0.z += v.z; a0.w += v.w; }
        if (m >= 2) { const float4 v = s_buf[w][slot][1][l];
                      a1.x += v.x; a1.y += v.y; a1.z += v.z; a1.w += v.w; }
        if (m >= 3) { const float4 v = s_buf[w][slot][2][l];
                      a0.x += v.x; a0.y += v.y; a0.z += v.z; a0.w += v.w; }
        if (m >= 4) { const float4 v = s_buf[w][slot][3][l];
                      a1.x += v.x; a1.y += v.y; a1.z += v.z; a1.w += v.w; }
        FILL(c + 2);
    }
#undef FILL

    float4 asum;
    asum.x = a0.x + a1.x;  asum.y = a0.y + a1.y;
    asum.z = a0.z + a1.z;  asum.w = a0.w + a1.w;
    *(float4*)&s_part[w][4 * l] = asum;
    __syncthreads();

    const float inv = 1.0f / (float)max(n, 1);
    g_sent[(size_t)seg * H + tid] =
        ((s_part[0][tid] + s_part[1][tid]) +
         (s_part[2][tid] + s_part[3][tid])) * inv;
}

// ---------------------------------------------------------------------------
// Kernel 2: MLP head + BCE. 8 rows per 256-thread block, k-SPLIT across the
// two 128-thread halves (half h covers k in [64h, 64h+64)) -> 512 blocks,
// double warps and half the dependent-chain length vs unsplit.
// ---------------------------------------------------------------------------
__global__ __launch_bounds__(256) void mlp_bce_kernel(
    const float* __restrict__ y_true,
    const float* __restrict__ W_hid,   // [H,H] row-major
    const float* __restrict__ b_hid,
    const float* __restrict__ W_out,
    const float* __restrict__ b_out,
    float*       __restrict__ out,
    int B)
{
    const int t    = threadIdx.x;
    const int row0 = blockIdx.x * RPB;
    const int kh   = t >> 7;           // k-half
    const int col  = t & 127;

    __shared__ float s_t[H][RPB];      // transposed sentence tile (4KB)
    __shared__ float s_p[2][RPB][H];   // per-half partials (8KB)
    __shared__ float red[RPB][4];

    for (int e = t; e < RPB * H; e += 256) {
        const int r = e >> 7;
        const int k = e & 127;
        const int row = min(row0 + r, B - 1);
        s_t[k][r] = g_sent[(size_t)row * H + k];
    }
    __syncthreads();

    float acc[RPB];
#pragma unroll
    for (int r = 0; r < RPB; r++) acc[r] = 0.f;

    const int k0 = kh * 64;
#pragma unroll 4
    for (int kk = 0; kk < 64; kk++) {
        const int k = k0 + kk;
        const float  wv = __ldg(&W_hid[k * H + col]);
        const float4 sa = *(const float4*)&s_t[k][0];   // broadcast LDS.128
        const float4 sb = *(const float4*)&s_t[k][4];
        acc[0] += sa.x * wv;  acc[1] += sa.y * wv;
        acc[2] += sa.z * wv;  acc[3] += sa.w * wv;
        acc[4] += sb.x * wv;  acc[5] += sb.y * wv;
        acc[6] += sb.z * wv;  acc[7] += sb.w * wv;
    }
#pragma unroll
    for (int r = 0; r < RPB; r++) s_p[kh][r][col] = acc[r];
    __syncthreads();

    if (t < 128) {                      // 4 warps finish up
        const float bh = b_hid[col];
        const float wo = W_out[col];
        float val[RPB];
#pragma unroll
        for (int r = 0; r < RPB; r++)
            val[r] = tanhf(s_p[0][r][col] + s_p[1][r][col] + bh) * wo;

#pragma unroll
        for (int off = 16; off > 0; off >>= 1)
#pragma unroll
            for (int r = 0; r < RPB; r++)
                val[r] += __shfl_xor_sync(0xffffffffu, val[r], off);

        if ((t & 31) == 0)
#pragma unroll
            for (int r = 0; r < RPB; r++) red[r][t >> 5] = val[r];
    }
    __syncthreads();

    if (t < RPB) {
        const int row = row0 + t;
        float loss = 0.f;
        if (row < B) {
            const float z = (red[t][0] + red[t][1]) +
                            (red[t][2] + red[t][3]) + __ldg(b_out);
            const float lp  = fmaxf(-log1pf(expf(-z)), -100.0f);
            const float l1m = fmaxf(-log1pf(expf(z)),  -100.0f);
            const float y   = __ldg(&y_true[row]);
            loss = -(y * lp + (1.0f - y) * l1m);
        }
#pragma unroll
        for (int off = 4; off > 0; off >>= 1)
            loss += __shfl_xor_sync(0x000000ffu, loss, off);
        if (t == 0) atomicAdd(out, loss);
    }
}

// ---------------------------------------------------------------------------
extern "C" void kernel_launch(void* const* d_in, const int* in_sizes, int n_in,
                              void* d_out, int out_size)
{
    const int*   token_ids = (const int*)d_in[0];
    const int*   seg_ids   = (const int*)d_in[1];
    const float* y_true    = (const float*)d_in[2];
    const float* embed     = (const float*)d_in[3];
    const float* W_hid     = (const float*)d_in[4];
    const float* b_hid     = (const float*)d_in[5];
    const float* W_out     = (const float*)d_in[6];
    const float* b_out     = (const float*)d_in[7];

    const int T = in_sizes[0];
    const int B = in_sizes[2];
    float* out = (float*)d_out;

    const int vthreads = (T + 3) / 4;
    prepass_kernel<<<(vthreads + 255) / 256, 256>>>(seg_ids, out, T, B);

    seg_mean_kernel<<<B, 128>>>(token_ids, embed);

    mlp_bce_kernel<<<(B + RPB - 1) / RPB, 256>>>(y_true, W_hid, b_hid,
                                                 W_out, b_out, out, B);
}